// round 2
// baseline (speedup 1.0000x reference)
#include <cuda_runtime.h>

#define NUPD   16
#define NMO    64
#define NCONF  64
#define NBATCH 4096
#define NELEC  32
#define RS     65   // padded shared row stride (floats) -> conflict-free gathers

__device__ __forceinline__ float fast_rcp(float x) {
    float r;
    asm("rcp.approx.f32 %0, %1;" : "=f"(r) : "f"(x));
    r = r * (2.0f - x * r);   // one Newton step -> ~1 ulp
    return r;
}

__global__ void __launch_bounds__(256) kinetic_kernel(
    const float* __restrict__ MO,
    const float* __restrict__ d2MO,
    const float* __restrict__ dJdMO,
    const float* __restrict__ d2JMO,
    const int*   __restrict__ cup,
    const int*   __restrict__ cdown,
    float*       __restrict__ out)   // [kinetic (B,NCONF) | det_prod (B,NCONF)]
{
    __shared__ float sM[NELEC * RS];
    __shared__ float sB[NELEC * RS];
    __shared__ int   sCfg[2 * NCONF * NUPD];

    const int b   = blockIdx.x;
    const int tid = threadIdx.x;

    // ---- stage configs (tiny, L2-hot) ----
    for (int i = tid; i < NCONF * NUPD; i += 256) {
        sCfg[i]                 = cup[i];
        sCfg[NCONF * NUPD + i]  = cdown[i];
    }

    // ---- stage MO rows + fused B = d2MO + 2*dJdMO + d2JMO for this batch ----
    const size_t base = (size_t)b * (NELEC * NMO);
    const float4* gM  = (const float4*)(MO    + base);
    const float4* gX  = (const float4*)(d2MO  + base);
    const float4* gY  = (const float4*)(dJdMO + base);
    const float4* gZ  = (const float4*)(d2JMO + base);
    #pragma unroll
    for (int r = 0; r < 2; ++r) {
        int i   = tid + r * 256;        // 0..511 float4s (2048 floats)
        int row = i >> 4;               // 16 float4 per 64-float row
        int c4  = i & 15;
        float4 m = gM[i];
        float4 x = gX[i];
        float4 y = gY[i];
        float4 z = gZ[i];
        float* pm = &sM[row * RS + c4 * 4];
        pm[0] = m.x; pm[1] = m.y; pm[2] = m.z; pm[3] = m.w;
        float* pb = &sB[row * RS + c4 * 4];
        pb[0] = x.x + 2.0f * y.x + z.x;
        pb[1] = x.y + 2.0f * y.y + z.y;
        pb[2] = x.z + 2.0f * y.z + z.z;
        pb[3] = x.w + 2.0f * y.w + z.w;
    }
    __syncthreads();

    // ---- warp layout: 2 sixteen-lane groups per warp = (spin up, spin down) of one config ----
    const int lane = tid & 31;
    const int warp = tid >> 5;
    const int half = lane >> 4;         // 0: up, 1: down
    const int l    = lane & 15;         // my row of the 16x16 system
    const unsigned FULL = 0xFFFFFFFFu;

    const float* myM   = &sM[(half * NUPD + l) * RS];
    const float* myB   = &sB[(half * NUPD + l) * RS];
    const int*   myCfg = &sCfg[half * (NCONF * NUPD)];

    #pragma unroll 1
    for (int it = 0; it < 8; ++it) {
        const int c = warp + it * 8;

        // gather my row of A and B (stride-65 -> distinct banks across lanes)
        float a[16], y[16];
        #pragma unroll
        for (int j = 0; j < 16; ++j) {
            int cj = myCfg[c * NUPD + j];
            a[j] = myM[cj];
            y[j] = myB[cj];
        }

        // ---- LU with partial pivoting on augmented [A | B], row-per-lane ----
        int   pivstep = -1;     // which elimination step I was pivot for
        float det     = 1.0f;   // product of pivots (identical on all lanes of group)
        float rdiag   = 1.0f;   // 1/u_kk of my pivot row
        float tcontrib= 0.0f;   // my diagonal element of X = A^-1 B
        int   virt    = l;      // virtual row position (permutation parity tracking)
        bool  neg     = false;

        #pragma unroll
        for (int k = 0; k < 16; ++k) {
            // pivot selection: max |a[k]| among not-yet-pivoted rows
            float cand = (pivstep < 0) ? fabsf(a[k]) : -1.0f;
            float bv = cand;
            #pragma unroll
            for (int off = 8; off; off >>= 1)
                bv = fmaxf(bv, __shfl_xor_sync(FULL, bv, off, 16));
            unsigned bal = __ballot_sync(FULL, cand == bv);
            int bl = __ffs(half ? (bal >> 16) : (bal & 0xFFFFu)) - 1; // group-local pivot lane

            float pv = __shfl_sync(FULL, a[k], bl, 16);

            // permutation sign via virtual swap
            int vb = __shfl_sync(FULL, virt, bl, 16);
            neg ^= (vb != k);
            bool ispiv = (l == bl);
            if (virt == k) virt = vb;
            if (ispiv)     virt = k;

            det *= pv;
            float rpv    = fast_rcp(pv);
            bool  active = (pivstep < 0) && !ispiv;
            if (ispiv) { pivstep = k; rdiag = rpv; }

            float m = active ? a[k] * rpv : 0.0f;   // 0 for pivot/finished rows
            #pragma unroll
            for (int j = k + 1; j < 16; ++j)
                a[j] -= m * __shfl_sync(FULL, a[j], bl, 16);
            #pragma unroll
            for (int j = 0; j < 16; ++j)
                y[j] -= m * __shfl_sync(FULL, y[j], bl, 16);
        }

        // ---- back substitution (rows stay unscaled; scale folded into coef) ----
        #pragma unroll
        for (int k = 15; k >= 0; --k) {
            unsigned bal = __ballot_sync(FULL, pivstep == k);
            int src = __ffs(half ? (bal >> 16) : (bal & 0xFFFFu)) - 1;
            float rk   = __shfl_sync(FULL, rdiag, src, 16);
            float coef = (pivstep < k) ? a[k] * rk : 0.0f;
            #pragma unroll
            for (int j = 0; j < 16; ++j) {
                float xk = __shfl_sync(FULL, y[j], src, 16);
                y[j] -= coef * xk;
            }
            if (pivstep == k) tcontrib = y[k] * rdiag;  // X[k][k]
        }

        // ---- reduce trace within group, combine spins across halves ----
        float tr = tcontrib;
        #pragma unroll
        for (int off = 8; off; off >>= 1)
            tr += __shfl_xor_sync(FULL, tr, off, 16);
        float sdet = neg ? -det : det;

        float tro  = __shfl_xor_sync(FULL, tr,   16);   // other spin (width 32)
        float deto = __shfl_xor_sync(FULL, sdet, 16);
        float detprod = sdet * deto;
        float kin = -0.5f * (tr + tro) * detprod;

        if (lane == 0) {
            out[(size_t)b * NCONF + c] = kin;
            out[(size_t)(NBATCH * NCONF) + (size_t)b * NCONF + c] = detprod;
        }
    }
}

extern "C" void kernel_launch(void* const* d_in, const int* in_sizes, int n_in,
                              void* d_out, int out_size) {
    (void)in_sizes; (void)n_in; (void)out_size;
    kinetic_kernel<<<NBATCH, 256>>>(
        (const float*)d_in[0],   // MO
        (const float*)d_in[1],   // d2MO
        (const float*)d_in[2],   // dJdMO
        (const float*)d_in[3],   // d2JMO
        (const int*)  d_in[4],   // cup
        (const int*)  d_in[5],   // cdown
        (float*)d_out);
}